// round 14
// baseline (speedup 1.0000x reference)
#include <cuda_runtime.h>
#include <stdint.h>

// Problem constants (fixed shapes for this problem instance)
#define A_CNT 200000   // total anchors
#define N_CNT 100000   // inside anchors
#define B_CNT 8        // batch
#define G_CNT 64       // gt boxes per batch
#define BN    800000   // B_CNT * N_CNT, elements per uniform stream
#define K_POS 128
#define EPS_F 1.1920929e-07f
#define NBIN  4096
#define CAPB  64       // per-bin bucket capacity (E[load]=24; overflow -> full-scan fallback)
#define CAP   4096     // fallback buffer capacity
#define FBLK  196      // ceil(N_CNT/512)   fused kernel geometry (512 anchors/block, 2/thread)
#define RBLK  49       // ceil(N_CNT/2048)  repair geometry (8 elems/thread)
#define SBLK  98       // ceil(N_CNT/1024)  scatter geometry (4 elems/thread)

typedef unsigned long long ull;

// ------------------------------ scratch ------------------------------------
__device__ int      g_label[B_CNT * N_CNT];
__device__ unsigned g_rbits[3 * BN];          // r1,r2,r3 raw uniform bits
__device__ int      g_gtmax[B_CNT * G_CNT];   // global per-gt max iou bits
__device__ int      g_blkmax[B_CNT * FBLK * G_CNT];  // per-fused-block local max

__device__ unsigned g_hist[B_CNT][3][NBIN];   // bin counts (r1|pos, r2|neg, r3|neg)
__device__ unsigned g_bucket[B_CNT][3][NBIN][CAPB];  // per-bin candidate indices
__device__ int      g_pos_cnt[B_CNT], g_neg_cnt[B_CNT];
__device__ int      g_mode[B_CNT];            // 0 none,1 demote-pos,2 promote-neg,3 promote-all
__device__ int      g_sel3[B_CNT];
__device__ ull      g_thr12[B_CNT], g_thr3[B_CNT];

// ------------------------------ threefry2x32-20 (JAX-exact) ----------------
__device__ __forceinline__ unsigned rotl32(unsigned v, int r) {
    return (v << r) | (v >> (32 - r));
}

__device__ __forceinline__ void tf2x32(unsigned k0, unsigned k1,
                                       unsigned x0, unsigned x1,
                                       unsigned& o0, unsigned& o1) {
    unsigned ks2 = k0 ^ k1 ^ 0x1BD11BDAu;
    x0 += k0; x1 += k1;
    x0 += x1; x1 = rotl32(x1, 13); x1 ^= x0;
    x0 += x1; x1 = rotl32(x1, 15); x1 ^= x0;
    x0 += x1; x1 = rotl32(x1, 26); x1 ^= x0;
    x0 += x1; x1 = rotl32(x1, 6);  x1 ^= x0;
    x0 += k1; x1 += ks2 + 1u;
    x0 += x1; x1 = rotl32(x1, 17); x1 ^= x0;
    x0 += x1; x1 = rotl32(x1, 29); x1 ^= x0;
    x0 += x1; x1 = rotl32(x1, 16); x1 ^= x0;
    x0 += x1; x1 = rotl32(x1, 24); x1 ^= x0;
    x0 += ks2; x1 += k0 + 2u;
    x0 += x1; x1 = rotl32(x1, 13); x1 ^= x0;
    x0 += x1; x1 = rotl32(x1, 15); x1 ^= x0;
    x0 += x1; x1 = rotl32(x1, 26); x1 ^= x0;
    x0 += x1; x1 = rotl32(x1, 6);  x1 ^= x0;
    x0 += k0; x1 += k1 + 3u;
    x0 += x1; x1 = rotl32(x1, 17); x1 ^= x0;
    x0 += x1; x1 = rotl32(x1, 29); x1 ^= x0;
    x0 += x1; x1 = rotl32(x1, 16); x1 ^= x0;
    x0 += x1; x1 = rotl32(x1, 24); x1 ^= x0;
    x0 += k1; x1 += ks2 + 4u;
    x0 += x1; x1 = rotl32(x1, 13); x1 ^= x0;
    x0 += x1; x1 = rotl32(x1, 15); x1 ^= x0;
    x0 += x1; x1 = rotl32(x1, 26); x1 ^= x0;
    x0 += x1; x1 = rotl32(x1, 6);  x1 ^= x0;
    x0 += ks2; x1 += k0 + 5u;
    o0 = x0; o1 = x1;
}

// ---------- merged init: rng + output fill + scratch reset ------------------
__global__ __launch_bounds__(256) void init_rng_kernel(float4* __restrict__ out4) {
    __shared__ unsigned sk[6];
    if (threadIdx.x < 3) {
        unsigned o0, o1;
        tf2x32(0u, 42u, 0u, (unsigned)threadIdx.x, o0, o1);
        sk[2 * threadIdx.x]     = o0;
        sk[2 * threadIdx.x + 1] = o1;
    }
    __syncthreads();
    unsigned gid = blockIdx.x * 256 + threadIdx.x;
    if (gid < 3u * BN) {
        int m = gid / BN;
        unsigned e = gid - (unsigned)m * BN;
        unsigned o0, o1;
        tf2x32(sk[2 * m], sk[2 * m + 1], 0u, e, o0, o1);
        g_rbits[gid] = o0 ^ o1;
    }
    const unsigned LBL4 = B_CNT * A_CNT / 4;   // 400000 float4 of -1
    const unsigned TOT4 = LBL4 * 5;            // 2M float4 total
    if (gid < TOT4)
        out4[gid] = (gid < LBL4) ? make_float4(-1.f, -1.f, -1.f, -1.f)
                                 : make_float4(0.f, 0.f, 0.f, 0.f);
    if (gid < B_CNT * 3 * NBIN) ((unsigned*)g_hist)[gid] = 0u;
    if (gid < B_CNT * G_CNT) g_gtmax[gid] = 0;
    if (gid < B_CNT) { g_pos_cnt[gid] = 0; g_neg_cnt[gid] = 0; }
}

// ---------- fused pass: labels (sans is_gt_max) + locs + per-gt maxes -------
// R10-proven structure; changes: unconditional smem atomicMax (semantics
// identical, drops an LDS pre-check per overlapping pair) + unroll 8.
__global__ __launch_bounds__(256) void fused_kernel(const float4* __restrict__ ianch,
                                                    const float4* __restrict__ gtb,
                                                    const float4* __restrict__ anch,
                                                    const int*    __restrict__ iidx,
                                                    float4*       __restrict__ out_bbox) {
    __shared__ float4 sg[G_CNT];
    __shared__ float  sag[G_CNT];
    __shared__ int    smax[G_CNT];
    int b = blockIdx.y;
    int t = threadIdx.x;
    if (t < G_CNT) {
        float4 g = gtb[b * G_CNT + t];
        sg[t]   = g;
        sag[t]  = (g.z - g.x) * (g.w - g.y);
        smax[t] = 0;
    }
    __syncthreads();
    int n0 = blockIdx.x * 512 + t;
    int n1 = n0 + 256;
    bool v0 = (n0 < N_CNT), v1 = (n1 < N_CNT);
    float4 a0 = v0 ? ianch[n0] : make_float4(0.f, 0.f, 0.f, 0.f);
    float4 a1 = v1 ? ianch[n1] : make_float4(0.f, 0.f, 0.f, 0.f);
    float area0 = (a0.z - a0.x) * (a0.w - a0.y);
    float area1 = (a1.z - a1.x) * (a1.w - a1.y);
    float amax0 = -1.0f, amax1 = -1.0f;
    int arg0 = 0, arg1 = 0;
#pragma unroll 8
    for (int g = 0; g < G_CNT; ++g) {
        float4 gb = sg[g];
        float ag = sag[g];
        float iw0 = fminf(a0.z, gb.z) - fmaxf(a0.x, gb.x);
        float ih0 = fminf(a0.w, gb.w) - fmaxf(a0.y, gb.y);
        float in0 = fmaxf(iw0, 0.0f) * fmaxf(ih0, 0.0f);
        float iw1 = fminf(a1.z, gb.z) - fmaxf(a1.x, gb.x);
        float ih1 = fminf(a1.w, gb.w) - fmaxf(a1.y, gb.y);
        float in1 = fmaxf(iw1, 0.0f) * fmaxf(ih1, 0.0f);
        float iou0 = 0.0f, iou1 = 0.0f;
        if (in0 > 0.0f) {
            iou0 = __fdiv_rn(in0, area0 + ag - in0);
            atomicMax(&smax[g], __float_as_int(iou0));
        }
        if (in1 > 0.0f) {
            iou1 = __fdiv_rn(in1, area1 + ag - in1);
            atomicMax(&smax[g], __float_as_int(iou1));
        }
        if (iou0 > amax0) { amax0 = iou0; arg0 = g; }  // first-index argmax (strict >)
        if (iou1 > amax1) { amax1 = iou1; arg1 = g; }
    }
#pragma unroll
    for (int s = 0; s < 2; ++s) {
        bool v = s ? v1 : v0;
        if (!v) continue;
        int n = s ? n1 : n0;
        float4 a = s ? a1 : a0;
        float amax = s ? amax1 : amax0;
        int arg = s ? arg1 : arg0;
        int lab = (amax >= 0.7f) ? 1 : ((amax < 0.3f) ? 0 : -1);
        g_label[b * N_CNT + n] = lab;

        float h0 = a.w - a.y, w0 = a.z - a.x;
        float cx = a.x - 0.5f * w0;
        float cy = a.y + 0.5f * h0;
        float hh = fmaxf(h0, EPS_F), ww = fmaxf(w0, EPS_F);
        float4 mb = anch[arg];
        float bh = mb.w - mb.y, bw = mb.z - mb.x;
        float bcx = mb.x + 0.5f * bw, bcy = mb.y + 0.5f * bh;
        float dx = __fdiv_rn(bcx - cx, ww);
        float dy = __fdiv_rn(bcy - cy, hh);
        float dwv = logf(__fdiv_rn(bw, ww));
        float dhv = logf(__fdiv_rn(bh, hh));
        out_bbox[(long)b * A_CNT + iidx[n]] = make_float4(dx, dy, dwv, dhv);
    }
    __syncthreads();
    if (t < G_CNT) {
        int v = smax[t];
        g_blkmax[(b * FBLK + blockIdx.x) * G_CNT + t] = v;
        if (v > 0) atomicMax(&g_gtmax[b * G_CNT + t], v);
    }
}

// ----- repair pass: is_gt_max override + histogram + bucket build -----------
// (R10-proven; unchanged) 8 anchors/thread, rbits loaded upfront (MLP=8).
__global__ __launch_bounds__(256) void repair_hist_kernel(const float4* __restrict__ ianch,
                                                          const float4* __restrict__ gtb) {
    __shared__ int    sgm[G_CNT];
    __shared__ float4 sg[G_CNT];
    __shared__ float  sag[G_CNT];
    __shared__ unsigned char glist[G_CNT];
    __shared__ int s_m;
    int b = blockIdx.y;
    int blk = blockIdx.x;          // covers anchors [blk*2048, blk*2048+2048)
    int t = threadIdx.x;
    if (t == 0) s_m = 0;
    __syncthreads();
    if (t < G_CNT) {
        int gm = g_gtmax[b * G_CNT + t];
        sgm[t] = gm;
        float4 g = gtb[b * G_CNT + t];
        sg[t]  = g;
        sag[t] = (g.z - g.x) * (g.w - g.y);
        int match = 0;
#pragma unroll
        for (int s = 0; s < 4; ++s) {   // 4 fused blocks (512 anchors each) per repair block
            int fb = blk * 4 + s;
            if (fb < FBLK && g_blkmax[(b * FBLK + fb) * G_CNT + t] == gm) match = 1;
        }
        if (match) {
            int idx = atomicAdd(&s_m, 1);
            glist[idx] = (unsigned char)t;
        }
    }
    __syncthreads();
    int m = s_m;
    int n0 = blk * 2048 + t * 8;
    if (n0 >= N_CNT) return;     // N_CNT % 8 == 0, so n0 < N implies all 8 valid
    int base = b * N_CNT + n0;
    int4 la = *(const int4*)&g_label[base];
    int4 lb = *(const int4*)&g_label[base + 4];
    uint4 r1a = *(const uint4*)&g_rbits[base];
    uint4 r1b = *(const uint4*)&g_rbits[base + 4];
    uint4 r2a = *(const uint4*)&g_rbits[BN + base];
    uint4 r2b = *(const uint4*)&g_rbits[BN + base + 4];
    uint4 r3a = *(const uint4*)&g_rbits[2 * BN + base];
    uint4 r3b = *(const uint4*)&g_rbits[2 * BN + base + 4];
    int labs[8] = {la.x, la.y, la.z, la.w, lb.x, lb.y, lb.z, lb.w};
    unsigned r1v[8] = {r1a.x, r1a.y, r1a.z, r1a.w, r1b.x, r1b.y, r1b.z, r1b.w};
    unsigned r2v[8] = {r2a.x, r2a.y, r2a.z, r2a.w, r2b.x, r2b.y, r2b.z, r2b.w};
    unsigned r3v[8] = {r3a.x, r3a.y, r3a.z, r3a.w, r3b.x, r3b.y, r3b.z, r3b.w};

    if (m > 0) {
        bool changed = false;
#pragma unroll
        for (int q = 0; q < 8; ++q) {
            if (labs[q] == 1) continue;
            int n = n0 + q;
            float4 a = ianch[n];
            float area_a = (a.z - a.x) * (a.w - a.y);
            bool eq = false;
            for (int j = 0; j < m; ++j) {
                int g = glist[j];
                float4 gb = sg[g];
                float iw = fminf(a.z, gb.z) - fmaxf(a.x, gb.x);
                float ih = fminf(a.w, gb.w) - fmaxf(a.y, gb.y);
                float inter = fmaxf(iw, 0.0f) * fmaxf(ih, 0.0f);
                float iou = (inter > 0.0f) ? __fdiv_rn(inter, area_a + sag[g] - inter) : 0.0f;
                eq |= (__float_as_int(iou) == sgm[g]);
            }
            if (eq) { labs[q] = 1; changed = true; }
        }
        if (changed) {
            *(int4*)&g_label[base]     = make_int4(labs[0], labs[1], labs[2], labs[3]);
            *(int4*)&g_label[base + 4] = make_int4(labs[4], labs[5], labs[6], labs[7]);
        }
    }

    // histogram final (pre-sampling) labels + bucket build
    int p = 0, ng = 0;
#pragma unroll
    for (int q = 0; q < 8; ++q) {
        unsigned n = (unsigned)(n0 + q);
        if (labs[q] == 1) {
            unsigned bin = r1v[q] >> 20;
            unsigned old = atomicAdd(&g_hist[b][0][bin], 1u);
            if (old < CAPB) g_bucket[b][0][bin][old] = n;
            ++p;
        } else if (labs[q] == 0) {
            unsigned bin2 = r2v[q] >> 20;
            unsigned old2 = atomicAdd(&g_hist[b][1][bin2], 1u);
            if (old2 < CAPB) g_bucket[b][1][bin2][old2] = n;
            unsigned bin3 = r3v[q] >> 20;
            unsigned old3 = atomicAdd(&g_hist[b][2][bin3], 1u);
            if (old3 < CAPB) g_bucket[b][2][bin3][old3] = n;
            ++ng;
        }
    }
#pragma unroll
    for (int o = 16; o > 0; o >>= 1) {
        p  += __shfl_down_sync(0xffffffffu, p, o);
        ng += __shfl_down_sync(0xffffffffu, ng, o);
    }
    if ((t & 31) == 0) {
        if (p)  atomicAdd(&g_pos_cnt[b], p);
        if (ng) atomicAdd(&g_neg_cnt[b], ng);
    }
}

// ------------------------------ sampling (one block per batch) --------------
// 40-bit rank key = (rbits>>9)<<17 | n. Top-12 bits = rbits>>20 (bin).
// In-bin 28-bit subkey = ((rbits>>9)&0x7FF)<<17 | n. Keys distinct.

__device__ void crossing1024(const int* __restrict__ H, int K, int& bin, int& rank,
                             int* warpsum, int* s_bin, int* s_rank) {
    int t = threadIdx.x, lane = t & 31, wid = t >> 5;
    int4 l4 = *(const int4*)&H[t * 4];
    int loc[4] = {l4.x, l4.y, l4.z, l4.w};
    int sum = loc[0] + loc[1] + loc[2] + loc[3];
    int incl = sum;
#pragma unroll
    for (int off = 1; off < 32; off <<= 1) {
        int v = __shfl_up_sync(0xffffffffu, incl, off);
        if (lane >= off) incl += v;
    }
    if (lane == 31) warpsum[wid] = incl;
    __syncthreads();
    if (wid == 0) {
        int ws = warpsum[lane];
#pragma unroll
        for (int off = 1; off < 32; off <<= 1) {
            int v = __shfl_up_sync(0xffffffffu, ws, off);
            if (lane >= off) ws += v;
        }
        warpsum[lane] = ws;
    }
    __syncthreads();
    int offset = wid ? warpsum[wid - 1] : 0;
    incl += offset;
    int excl = incl - sum;
    if (excl < K && K <= incl) {
        int kk = K - excl;
#pragma unroll
        for (int i = 0; i < 4; ++i) {
            if (kk <= loc[i]) { *s_bin = t * 4 + i; *s_rank = kk; break; }
            kk -= loc[i];
        }
    }
    __syncthreads();
    bin = *s_bin;
    rank = *s_rank;
}

__device__ void resolve1024(const unsigned* sbuf, int c, int rank, int bin, ull* s_thr) {
    for (int i = threadIdx.x; i < c; i += 1024) {
        unsigned k = sbuf[i];
        int cnt = 0;
        for (int j = 0; j < c; ++j) cnt += (sbuf[j] < k);
        if (cnt == rank - 1) *s_thr = ((ull)bin << 28) | (ull)k;
    }
    __syncthreads();
}

__global__ __launch_bounds__(1024) void sample_kernel() {
    int b = blockIdx.x;
    int t = threadIdx.x;
    __shared__ __align__(16) int h3[NBIN];
    __shared__ __align__(16) unsigned buf[CAP];
    __shared__ int warpsum[32];
    __shared__ int s_bin, s_rank, s_cnt;
    __shared__ ull s_thr;

    {   // copy neg-stage-3 histogram to smem (one int4 per thread)
        int4 v = *(const int4*)&g_hist[b][2][t * 4];
        *(int4*)&h3[t * 4] = v;
    }
    int pos = g_pos_cnt[b], neg = g_neg_cnt[b];
    int mode = 0, K = 0;
    if (pos > K_POS) { mode = 1; K = K_POS; }
    else {
        int need = K_POS - pos;
        if (need > 0) { if (neg > need) { mode = 2; K = need; } else mode = 3; }
    }
    if (t == 0) g_mode[b] = mode;
    int* lab = g_label + b * N_CNT;
    const unsigned* r2 = g_rbits + BN + b * N_CNT;
    const unsigned* r3 = g_rbits + 2 * BN + b * N_CNT;
    __syncthreads();

    if (mode == 1 || mode == 2) {
        int h = (mode == 1) ? 0 : 1;
        const int* H = (const int*)g_hist[b][h];
        int bin, rank;
        crossing1024(H, K, bin, rank, warpsum, &s_bin, &s_rank);
        const unsigned* rr = (mode == 1) ? (g_rbits + b * N_CNT) : r2;
        int cbin = H[bin];
        int c;
        if (cbin <= CAPB) {
            // bucket fast path: all bin members are in the bucket
            if (t < cbin) {
                unsigned n = g_bucket[b][h][bin][t];
                unsigned rb = rr[n];
                buf[t] = (((rb >> 9) & 0x7FFu) << 17) | n;
            }
            c = cbin;
            __syncthreads();
        } else {
            // fallback: full scan
            if (t == 0) s_cnt = 0;
            __syncthreads();
            int want = (mode == 1) ? 1 : 0;
            for (int n = t * 4; n < N_CNT; n += 4096) {
                int4 l4 = *(const int4*)&lab[n];
                uint4 r4 = *(const uint4*)&rr[n];
                const int* lq = (const int*)&l4;
                const unsigned* rq = (const unsigned*)&r4;
#pragma unroll
                for (int q = 0; q < 4; ++q)
                    if (lq[q] == want && (int)(rq[q] >> 20) == bin) {
                        int idx = atomicAdd(&s_cnt, 1);
                        if (idx < CAP)
                            buf[idx] = (((rq[q] >> 9) & 0x7FFu) << 17) | (unsigned)(n + q);
                    }
            }
            __syncthreads();
            c = min(s_cnt, CAP);
        }
        resolve1024(buf, c, rank, bin, &s_thr);
        if (t == 0) g_thr12[b] = s_thr;
        if (mode == 2) {
            // promote negs with key <= T; candidates live in bins [0, bin]
            ull T = s_thr;
            bool ok = true;
            for (int bb = 0; bb <= bin; ++bb) ok &= ((const int*)g_hist[b][1])[bb] <= CAPB;
            if (ok) {
                for (int bb = 0; bb <= bin; ++bb) {
                    int c1 = ((const int*)g_hist[b][1])[bb];
                    for (int i = t; i < c1; i += 1024) {
                        unsigned n = g_bucket[b][1][bb][i];
                        bool take = (bb < bin);
                        if (!take) {
                            ull key = ((ull)(r2[n] >> 9) << 17) | n;
                            take = (key <= T);
                        }
                        if (take) {
                            lab[n] = 1;
                            atomicSub(&h3[r3[n] >> 20], 1);
                        }
                    }
                }
            } else {
                for (int n = t * 4; n < N_CNT; n += 4096) {
                    int4 l4 = *(const int4*)&lab[n];
                    const int* lq = (const int*)&l4;
                    bool any0 = (lq[0] == 0) | (lq[1] == 0) | (lq[2] == 0) | (lq[3] == 0);
                    if (!any0) continue;
                    uint4 r4 = *(const uint4*)&r2[n];
                    const unsigned* rq = (const unsigned*)&r4;
#pragma unroll
                    for (int q = 0; q < 4; ++q)
                        if (lq[q] == 0) {
                            ull key = ((ull)(rq[q] >> 9) << 17) | (unsigned)(n + q);
                            if (key <= T) {
                                lab[n + q] = 1;
                                atomicSub(&h3[r3[n + q] >> 20], 1);
                            }
                        }
                }
            }
            __syncthreads();
        }
    }
    // mode 1 demotion and mode 3 promotion are deferred to the scatter kernel.

    int neg2 = (mode == 2) ? neg - K : (mode == 3 ? 0 : neg);
    int sel3 = (neg2 > K_POS);
    if (t == 0) g_sel3[b] = sel3;
    if (sel3) {
        int bin, rank;
        crossing1024(h3, K_POS, bin, rank, warpsum, &s_bin, &s_rank);
        if (t == 0) s_cnt = 0;
        __syncthreads();
        int c3build = ((const int*)g_hist[b][2])[bin];  // build-time count bounds bucket validity
        int c;
        if (c3build <= CAPB) {
            if (t < c3build) {
                unsigned n = g_bucket[b][2][bin][t];
                if (lab[n] == 0) {   // exclude negs promoted in mode 2
                    int idx = atomicAdd(&s_cnt, 1);
                    unsigned rb = r3[n];
                    buf[idx] = (((rb >> 9) & 0x7FFu) << 17) | n;
                }
            }
            __syncthreads();
            c = s_cnt;
        } else {
            for (int n = t * 4; n < N_CNT; n += 4096) {
                int4 l4 = *(const int4*)&lab[n];
                uint4 r4 = *(const uint4*)&r3[n];
                const int* lq = (const int*)&l4;
                const unsigned* rq = (const unsigned*)&r4;
#pragma unroll
                for (int q = 0; q < 4; ++q)
                    if (lq[q] == 0 && (int)(rq[q] >> 20) == bin) {
                        int idx = atomicAdd(&s_cnt, 1);
                        if (idx < CAP)
                            buf[idx] = (((rq[q] >> 9) & 0x7FFu) << 17) | (unsigned)(n + q);
                    }
            }
            __syncthreads();
            c = min(s_cnt, CAP);
        }
        resolve1024(buf, c, rank, bin, &s_thr);
        if (t == 0) g_thr3[b] = s_thr;
    }
}

// ---- final scatter: apply deferred mode-1/3 + stage-3, write labels --------
__global__ __launch_bounds__(256) void scatter_kernel(const int* __restrict__ iidx,
                                                      float* __restrict__ out) {
    int b = blockIdx.y;
    int n0 = blockIdx.x * 1024 + threadIdx.x * 4;
    if (n0 >= N_CNT) return;
    int base = b * N_CNT + n0;
    int4 lab4 = *(const int4*)&g_label[base];
    int labs[4] = {lab4.x, lab4.y, lab4.z, lab4.w};
    int4 idx4 = *(const int4*)&iidx[n0];
    int idxs[4] = {idx4.x, idx4.y, idx4.z, idx4.w};
    int mode = g_mode[b];
    if (mode == 1) {
        bool any1 = (labs[0] == 1) | (labs[1] == 1) | (labs[2] == 1) | (labs[3] == 1);
        if (any1) {
            uint4 rb1 = *(const uint4*)&g_rbits[base];
            const unsigned* r1v = (const unsigned*)&rb1;
            ull T = g_thr12[b];
#pragma unroll
            for (int q = 0; q < 4; ++q)
                if (labs[q] == 1) {
                    ull key = ((ull)(r1v[q] >> 9) << 17) | (unsigned)(n0 + q);
                    if (key > T) labs[q] = -1;
                }
        }
    } else if (mode == 3) {
#pragma unroll
        for (int q = 0; q < 4; ++q)
            if (labs[q] == 0) labs[q] = 1;
    }
    if (g_sel3[b]) {
        bool any0 = (labs[0] == 0) | (labs[1] == 0) | (labs[2] == 0) | (labs[3] == 0);
        if (any0) {
            uint4 rb3 = *(const uint4*)&g_rbits[2 * BN + base];
            const unsigned* r3v = (const unsigned*)&rb3;
            ull T = g_thr3[b];
#pragma unroll
            for (int q = 0; q < 4; ++q)
                if (labs[q] == 0) {
                    ull key = ((ull)(r3v[q] >> 9) << 17) | (unsigned)(n0 + q);
                    if (key > T) labs[q] = -1;
                }
        }
    }
    float* ob = out + (long)b * A_CNT;
#pragma unroll
    for (int q = 0; q < 4; ++q) ob[idxs[q]] = (float)labs[q];
}

// ------------------------------ launch --------------------------------------
extern "C" void kernel_launch(void* const* d_in, const int* in_sizes, int n_in,
                              void* d_out, int out_size) {
    const float* anch = nullptr;   // anchor_boxes        (200000,4) -> 800000
    const float* ianch = nullptr;  // inside_anchor_boxes (100000,4) -> 400000
    const float* gtb = nullptr;    // gt_boxes            (8,64,4)   -> 2048
    const int*   iidx = nullptr;   // inside_index        (100000)
    for (int i = 0; i < n_in; ++i) {
        switch (in_sizes[i]) {
            case 800000: anch  = (const float*)d_in[i]; break;
            case 400000: ianch = (const float*)d_in[i]; break;
            case 2048:   gtb   = (const float*)d_in[i]; break;
            case 100000: iidx  = (const int*)d_in[i];   break;
            default: break;
        }
    }
    float* out = (float*)d_out;
    const long LBL = (long)B_CNT * A_CNT;

    init_rng_kernel<<<(3 * BN + 255) / 256, 256>>>((float4*)out);

    dim3 gF(FBLK, B_CNT);
    fused_kernel<<<gF, 256>>>((const float4*)ianch, (const float4*)gtb,
                              (const float4*)anch, iidx,
                              (float4*)(out + LBL));
    dim3 gR(RBLK, B_CNT);
    repair_hist_kernel<<<gR, 256>>>((const float4*)ianch, (const float4*)gtb);
    sample_kernel<<<B_CNT, 1024>>>();
    dim3 gS(SBLK, B_CNT);
    scatter_kernel<<<gS, 256>>>(iidx, out);
}

// round 15
// speedup vs baseline: 1.0173x; 1.0173x over previous
#include <cuda_runtime.h>
#include <stdint.h>

// Problem constants (fixed shapes for this problem instance)
#define A_CNT 200000   // total anchors
#define N_CNT 100000   // inside anchors
#define B_CNT 8        // batch
#define G_CNT 64       // gt boxes per batch
#define BN    800000   // B_CNT * N_CNT, elements per uniform stream
#define K_POS 128
#define EPS_F 1.1920929e-07f
#define NBIN  4096
#define CAPB  64       // per-bin bucket capacity (E[load]=24; overflow -> full-scan fallback)
#define CAP   4096     // fallback buffer capacity
#define FBLK  196      // ceil(N_CNT/512)   fused kernel geometry (512 anchors/block, 2/thread)
#define RBLK  49       // ceil(N_CNT/2048)  repair geometry (8 elems/thread)
#define SBLK  98       // ceil(N_CNT/1024)  scatter geometry (4 elems/thread)

typedef unsigned long long ull;

// ------------------------------ scratch ------------------------------------
__device__ int      g_label[B_CNT * N_CNT];
__device__ unsigned g_rbits[3 * BN];          // r1,r2,r3 raw uniform bits
__device__ int      g_gtmax[B_CNT * G_CNT];   // global per-gt max iou bits
__device__ int      g_blkmax[B_CNT * FBLK * G_CNT];  // per-fused-block local max

__device__ unsigned g_hist[B_CNT][3][NBIN];   // bin counts (r1|pos, r2|neg, r3|neg)
__device__ unsigned g_bucket[B_CNT][3][NBIN][CAPB];  // per-bin candidate indices
__device__ int      g_pos_cnt[B_CNT], g_neg_cnt[B_CNT];
__device__ int      g_mode[B_CNT];            // 0 none,1 demote-pos,2 promote-neg,3 promote-all
__device__ int      g_sel3[B_CNT];
__device__ ull      g_thr12[B_CNT], g_thr3[B_CNT];

// ------------------------------ threefry2x32-20 (JAX-exact) ----------------
__device__ __forceinline__ unsigned rotl32(unsigned v, int r) {
    return (v << r) | (v >> (32 - r));
}

__device__ __forceinline__ void tf2x32(unsigned k0, unsigned k1,
                                       unsigned x0, unsigned x1,
                                       unsigned& o0, unsigned& o1) {
    unsigned ks2 = k0 ^ k1 ^ 0x1BD11BDAu;
    x0 += k0; x1 += k1;
    x0 += x1; x1 = rotl32(x1, 13); x1 ^= x0;
    x0 += x1; x1 = rotl32(x1, 15); x1 ^= x0;
    x0 += x1; x1 = rotl32(x1, 26); x1 ^= x0;
    x0 += x1; x1 = rotl32(x1, 6);  x1 ^= x0;
    x0 += k1; x1 += ks2 + 1u;
    x0 += x1; x1 = rotl32(x1, 17); x1 ^= x0;
    x0 += x1; x1 = rotl32(x1, 29); x1 ^= x0;
    x0 += x1; x1 = rotl32(x1, 16); x1 ^= x0;
    x0 += x1; x1 = rotl32(x1, 24); x1 ^= x0;
    x0 += ks2; x1 += k0 + 2u;
    x0 += x1; x1 = rotl32(x1, 13); x1 ^= x0;
    x0 += x1; x1 = rotl32(x1, 15); x1 ^= x0;
    x0 += x1; x1 = rotl32(x1, 26); x1 ^= x0;
    x0 += x1; x1 = rotl32(x1, 6);  x1 ^= x0;
    x0 += k0; x1 += k1 + 3u;
    x0 += x1; x1 = rotl32(x1, 17); x1 ^= x0;
    x0 += x1; x1 = rotl32(x1, 29); x1 ^= x0;
    x0 += x1; x1 = rotl32(x1, 16); x1 ^= x0;
    x0 += x1; x1 = rotl32(x1, 24); x1 ^= x0;
    x0 += k1; x1 += ks2 + 4u;
    x0 += x1; x1 = rotl32(x1, 13); x1 ^= x0;
    x0 += x1; x1 = rotl32(x1, 15); x1 ^= x0;
    x0 += x1; x1 = rotl32(x1, 26); x1 ^= x0;
    x0 += x1; x1 = rotl32(x1, 6);  x1 ^= x0;
    x0 += ks2; x1 += k0 + 5u;
    o0 = x0; o1 = x1;
}

// ---------- merged init: rng + output fill + scratch reset ------------------
__global__ __launch_bounds__(256) void init_rng_kernel(float4* __restrict__ out4) {
    __shared__ unsigned sk[6];
    if (threadIdx.x < 3) {
        unsigned o0, o1;
        tf2x32(0u, 42u, 0u, (unsigned)threadIdx.x, o0, o1);
        sk[2 * threadIdx.x]     = o0;
        sk[2 * threadIdx.x + 1] = o1;
    }
    __syncthreads();
    unsigned gid = blockIdx.x * 256 + threadIdx.x;
    if (gid < 3u * BN) {
        int m = gid / BN;
        unsigned e = gid - (unsigned)m * BN;
        unsigned o0, o1;
        tf2x32(sk[2 * m], sk[2 * m + 1], 0u, e, o0, o1);
        g_rbits[gid] = o0 ^ o1;
    }
    const unsigned LBL4 = B_CNT * A_CNT / 4;   // 400000 float4 of -1
    const unsigned TOT4 = LBL4 * 5;            // 2M float4 total
    if (gid < TOT4)
        out4[gid] = (gid < LBL4) ? make_float4(-1.f, -1.f, -1.f, -1.f)
                                 : make_float4(0.f, 0.f, 0.f, 0.f);
    if (gid < B_CNT * 3 * NBIN) ((unsigned*)g_hist)[gid] = 0u;
    if (gid < B_CNT * G_CNT) g_gtmax[gid] = 0;
    if (gid < B_CNT) { g_pos_cnt[gid] = 0; g_neg_cnt[gid] = 0; }
}

// ---------- fused pass: labels (sans is_gt_max) + locs + per-gt maxes -------
// R10-proven structure; changes: unconditional smem atomicMax (semantics
// identical, drops an LDS pre-check per overlapping pair) + unroll 8.
__global__ __launch_bounds__(256) void fused_kernel(const float4* __restrict__ ianch,
                                                    const float4* __restrict__ gtb,
                                                    const float4* __restrict__ anch,
                                                    const int*    __restrict__ iidx,
                                                    float4*       __restrict__ out_bbox) {
    __shared__ float4 sg[G_CNT];
    __shared__ float  sag[G_CNT];
    __shared__ int    smax[G_CNT];
    int b = blockIdx.y;
    int t = threadIdx.x;
    if (t < G_CNT) {
        float4 g = gtb[b * G_CNT + t];
        sg[t]   = g;
        sag[t]  = (g.z - g.x) * (g.w - g.y);
        smax[t] = 0;
    }
    __syncthreads();
    int n0 = blockIdx.x * 512 + t;
    int n1 = n0 + 256;
    bool v0 = (n0 < N_CNT), v1 = (n1 < N_CNT);
    float4 a0 = v0 ? ianch[n0] : make_float4(0.f, 0.f, 0.f, 0.f);
    float4 a1 = v1 ? ianch[n1] : make_float4(0.f, 0.f, 0.f, 0.f);
    float area0 = (a0.z - a0.x) * (a0.w - a0.y);
    float area1 = (a1.z - a1.x) * (a1.w - a1.y);
    float amax0 = -1.0f, amax1 = -1.0f;
    int arg0 = 0, arg1 = 0;
#pragma unroll 8
    for (int g = 0; g < G_CNT; ++g) {
        float4 gb = sg[g];
        float ag = sag[g];
        float iw0 = fminf(a0.z, gb.z) - fmaxf(a0.x, gb.x);
        float ih0 = fminf(a0.w, gb.w) - fmaxf(a0.y, gb.y);
        float in0 = fmaxf(iw0, 0.0f) * fmaxf(ih0, 0.0f);
        float iw1 = fminf(a1.z, gb.z) - fmaxf(a1.x, gb.x);
        float ih1 = fminf(a1.w, gb.w) - fmaxf(a1.y, gb.y);
        float in1 = fmaxf(iw1, 0.0f) * fmaxf(ih1, 0.0f);
        float iou0 = 0.0f, iou1 = 0.0f;
        if (in0 > 0.0f) {
            iou0 = __fdiv_rn(in0, area0 + ag - in0);
            atomicMax(&smax[g], __float_as_int(iou0));
        }
        if (in1 > 0.0f) {
            iou1 = __fdiv_rn(in1, area1 + ag - in1);
            atomicMax(&smax[g], __float_as_int(iou1));
        }
        if (iou0 > amax0) { amax0 = iou0; arg0 = g; }  // first-index argmax (strict >)
        if (iou1 > amax1) { amax1 = iou1; arg1 = g; }
    }
#pragma unroll
    for (int s = 0; s < 2; ++s) {
        bool v = s ? v1 : v0;
        if (!v) continue;
        int n = s ? n1 : n0;
        float4 a = s ? a1 : a0;
        float amax = s ? amax1 : amax0;
        int arg = s ? arg1 : arg0;
        int lab = (amax >= 0.7f) ? 1 : ((amax < 0.3f) ? 0 : -1);
        g_label[b * N_CNT + n] = lab;

        float h0 = a.w - a.y, w0 = a.z - a.x;
        float cx = a.x - 0.5f * w0;
        float cy = a.y + 0.5f * h0;
        float hh = fmaxf(h0, EPS_F), ww = fmaxf(w0, EPS_F);
        float4 mb = anch[arg];
        float bh = mb.w - mb.y, bw = mb.z - mb.x;
        float bcx = mb.x + 0.5f * bw, bcy = mb.y + 0.5f * bh;
        float dx = __fdiv_rn(bcx - cx, ww);
        float dy = __fdiv_rn(bcy - cy, hh);
        float dwv = logf(__fdiv_rn(bw, ww));
        float dhv = logf(__fdiv_rn(bh, hh));
        out_bbox[(long)b * A_CNT + iidx[n]] = make_float4(dx, dy, dwv, dhv);
    }
    __syncthreads();
    if (t < G_CNT) {
        int v = smax[t];
        g_blkmax[(b * FBLK + blockIdx.x) * G_CNT + t] = v;
        if (v > 0) atomicMax(&g_gtmax[b * G_CNT + t], v);
    }
}

// ----- repair pass: is_gt_max override + histogram + bucket build -----------
// (R10-proven; unchanged) 8 anchors/thread, rbits loaded upfront (MLP=8).
__global__ __launch_bounds__(256) void repair_hist_kernel(const float4* __restrict__ ianch,
                                                          const float4* __restrict__ gtb) {
    __shared__ int    sgm[G_CNT];
    __shared__ float4 sg[G_CNT];
    __shared__ float  sag[G_CNT];
    __shared__ unsigned char glist[G_CNT];
    __shared__ int s_m;
    int b = blockIdx.y;
    int blk = blockIdx.x;          // covers anchors [blk*2048, blk*2048+2048)
    int t = threadIdx.x;
    if (t == 0) s_m = 0;
    __syncthreads();
    if (t < G_CNT) {
        int gm = g_gtmax[b * G_CNT + t];
        sgm[t] = gm;
        float4 g = gtb[b * G_CNT + t];
        sg[t]  = g;
        sag[t] = (g.z - g.x) * (g.w - g.y);
        int match = 0;
#pragma unroll
        for (int s = 0; s < 4; ++s) {   // 4 fused blocks (512 anchors each) per repair block
            int fb = blk * 4 + s;
            if (fb < FBLK && g_blkmax[(b * FBLK + fb) * G_CNT + t] == gm) match = 1;
        }
        if (match) {
            int idx = atomicAdd(&s_m, 1);
            glist[idx] = (unsigned char)t;
        }
    }
    __syncthreads();
    int m = s_m;
    int n0 = blk * 2048 + t * 8;
    if (n0 >= N_CNT) return;     // N_CNT % 8 == 0, so n0 < N implies all 8 valid
    int base = b * N_CNT + n0;
    int4 la = *(const int4*)&g_label[base];
    int4 lb = *(const int4*)&g_label[base + 4];
    uint4 r1a = *(const uint4*)&g_rbits[base];
    uint4 r1b = *(const uint4*)&g_rbits[base + 4];
    uint4 r2a = *(const uint4*)&g_rbits[BN + base];
    uint4 r2b = *(const uint4*)&g_rbits[BN + base + 4];
    uint4 r3a = *(const uint4*)&g_rbits[2 * BN + base];
    uint4 r3b = *(const uint4*)&g_rbits[2 * BN + base + 4];
    int labs[8] = {la.x, la.y, la.z, la.w, lb.x, lb.y, lb.z, lb.w};
    unsigned r1v[8] = {r1a.x, r1a.y, r1a.z, r1a.w, r1b.x, r1b.y, r1b.z, r1b.w};
    unsigned r2v[8] = {r2a.x, r2a.y, r2a.z, r2a.w, r2b.x, r2b.y, r2b.z, r2b.w};
    unsigned r3v[8] = {r3a.x, r3a.y, r3a.z, r3a.w, r3b.x, r3b.y, r3b.z, r3b.w};

    if (m > 0) {
        bool changed = false;
#pragma unroll
        for (int q = 0; q < 8; ++q) {
            if (labs[q] == 1) continue;
            int n = n0 + q;
            float4 a = ianch[n];
            float area_a = (a.z - a.x) * (a.w - a.y);
            bool eq = false;
            for (int j = 0; j < m; ++j) {
                int g = glist[j];
                float4 gb = sg[g];
                float iw = fminf(a.z, gb.z) - fmaxf(a.x, gb.x);
                float ih = fminf(a.w, gb.w) - fmaxf(a.y, gb.y);
                float inter = fmaxf(iw, 0.0f) * fmaxf(ih, 0.0f);
                float iou = (inter > 0.0f) ? __fdiv_rn(inter, area_a + sag[g] - inter) : 0.0f;
                eq |= (__float_as_int(iou) == sgm[g]);
            }
            if (eq) { labs[q] = 1; changed = true; }
        }
        if (changed) {
            *(int4*)&g_label[base]     = make_int4(labs[0], labs[1], labs[2], labs[3]);
            *(int4*)&g_label[base + 4] = make_int4(labs[4], labs[5], labs[6], labs[7]);
        }
    }

    // histogram final (pre-sampling) labels + bucket build
    int p = 0, ng = 0;
#pragma unroll
    for (int q = 0; q < 8; ++q) {
        unsigned n = (unsigned)(n0 + q);
        if (labs[q] == 1) {
            unsigned bin = r1v[q] >> 20;
            unsigned old = atomicAdd(&g_hist[b][0][bin], 1u);
            if (old < CAPB) g_bucket[b][0][bin][old] = n;
            ++p;
        } else if (labs[q] == 0) {
            unsigned bin2 = r2v[q] >> 20;
            unsigned old2 = atomicAdd(&g_hist[b][1][bin2], 1u);
            if (old2 < CAPB) g_bucket[b][1][bin2][old2] = n;
            unsigned bin3 = r3v[q] >> 20;
            unsigned old3 = atomicAdd(&g_hist[b][2][bin3], 1u);
            if (old3 < CAPB) g_bucket[b][2][bin3][old3] = n;
            ++ng;
        }
    }
#pragma unroll
    for (int o = 16; o > 0; o >>= 1) {
        p  += __shfl_down_sync(0xffffffffu, p, o);
        ng += __shfl_down_sync(0xffffffffu, ng, o);
    }
    if ((t & 31) == 0) {
        if (p)  atomicAdd(&g_pos_cnt[b], p);
        if (ng) atomicAdd(&g_neg_cnt[b], ng);
    }
}

// ------------------------------ sampling (one block per batch) --------------
// 40-bit rank key = (rbits>>9)<<17 | n. Top-12 bits = rbits>>20 (bin).
// In-bin 28-bit subkey = ((rbits>>9)&0x7FF)<<17 | n. Keys distinct.

__device__ void crossing1024(const int* __restrict__ H, int K, int& bin, int& rank,
                             int* warpsum, int* s_bin, int* s_rank) {
    int t = threadIdx.x, lane = t & 31, wid = t >> 5;
    int4 l4 = *(const int4*)&H[t * 4];
    int loc[4] = {l4.x, l4.y, l4.z, l4.w};
    int sum = loc[0] + loc[1] + loc[2] + loc[3];
    int incl = sum;
#pragma unroll
    for (int off = 1; off < 32; off <<= 1) {
        int v = __shfl_up_sync(0xffffffffu, incl, off);
        if (lane >= off) incl += v;
    }
    if (lane == 31) warpsum[wid] = incl;
    __syncthreads();
    if (wid == 0) {
        int ws = warpsum[lane];
#pragma unroll
        for (int off = 1; off < 32; off <<= 1) {
            int v = __shfl_up_sync(0xffffffffu, ws, off);
            if (lane >= off) ws += v;
        }
        warpsum[lane] = ws;
    }
    __syncthreads();
    int offset = wid ? warpsum[wid - 1] : 0;
    incl += offset;
    int excl = incl - sum;
    if (excl < K && K <= incl) {
        int kk = K - excl;
#pragma unroll
        for (int i = 0; i < 4; ++i) {
            if (kk <= loc[i]) { *s_bin = t * 4 + i; *s_rank = kk; break; }
            kk -= loc[i];
        }
    }
    __syncthreads();
    bin = *s_bin;
    rank = *s_rank;
}

__device__ void resolve1024(const unsigned* sbuf, int c, int rank, int bin, ull* s_thr) {
    for (int i = threadIdx.x; i < c; i += 1024) {
        unsigned k = sbuf[i];
        int cnt = 0;
        for (int j = 0; j < c; ++j) cnt += (sbuf[j] < k);
        if (cnt == rank - 1) *s_thr = ((ull)bin << 28) | (ull)k;
    }
    __syncthreads();
}

__global__ __launch_bounds__(1024) void sample_kernel() {
    int b = blockIdx.x;
    int t = threadIdx.x;
    __shared__ __align__(16) int h3[NBIN];
    __shared__ __align__(16) unsigned buf[CAP];
    __shared__ int warpsum[32];
    __shared__ int s_bin, s_rank, s_cnt;
    __shared__ ull s_thr;

    {   // copy neg-stage-3 histogram to smem (one int4 per thread)
        int4 v = *(const int4*)&g_hist[b][2][t * 4];
        *(int4*)&h3[t * 4] = v;
    }
    int pos = g_pos_cnt[b], neg = g_neg_cnt[b];
    int mode = 0, K = 0;
    if (pos > K_POS) { mode = 1; K = K_POS; }
    else {
        int need = K_POS - pos;
        if (need > 0) { if (neg > need) { mode = 2; K = need; } else mode = 3; }
    }
    if (t == 0) g_mode[b] = mode;
    int* lab = g_label + b * N_CNT;
    const unsigned* r2 = g_rbits + BN + b * N_CNT;
    const unsigned* r3 = g_rbits + 2 * BN + b * N_CNT;
    __syncthreads();

    if (mode == 1 || mode == 2) {
        int h = (mode == 1) ? 0 : 1;
        const int* H = (const int*)g_hist[b][h];
        int bin, rank;
        crossing1024(H, K, bin, rank, warpsum, &s_bin, &s_rank);
        const unsigned* rr = (mode == 1) ? (g_rbits + b * N_CNT) : r2;
        int cbin = H[bin];
        int c;
        if (cbin <= CAPB) {
            // bucket fast path: all bin members are in the bucket
            if (t < cbin) {
                unsigned n = g_bucket[b][h][bin][t];
                unsigned rb = rr[n];
                buf[t] = (((rb >> 9) & 0x7FFu) << 17) | n;
            }
            c = cbin;
            __syncthreads();
        } else {
            // fallback: full scan
            if (t == 0) s_cnt = 0;
            __syncthreads();
            int want = (mode == 1) ? 1 : 0;
            for (int n = t * 4; n < N_CNT; n += 4096) {
                int4 l4 = *(const int4*)&lab[n];
                uint4 r4 = *(const uint4*)&rr[n];
                const int* lq = (const int*)&l4;
                const unsigned* rq = (const unsigned*)&r4;
#pragma unroll
                for (int q = 0; q < 4; ++q)
                    if (lq[q] == want && (int)(rq[q] >> 20) == bin) {
                        int idx = atomicAdd(&s_cnt, 1);
                        if (idx < CAP)
                            buf[idx] = (((rq[q] >> 9) & 0x7FFu) << 17) | (unsigned)(n + q);
                    }
            }
            __syncthreads();
            c = min(s_cnt, CAP);
        }
        resolve1024(buf, c, rank, bin, &s_thr);
        if (t == 0) g_thr12[b] = s_thr;
        if (mode == 2) {
            // promote negs with key <= T; candidates live in bins [0, bin]
            ull T = s_thr;
            bool ok = true;
            for (int bb = 0; bb <= bin; ++bb) ok &= ((const int*)g_hist[b][1])[bb] <= CAPB;
            if (ok) {
                for (int bb = 0; bb <= bin; ++bb) {
                    int c1 = ((const int*)g_hist[b][1])[bb];
                    for (int i = t; i < c1; i += 1024) {
                        unsigned n = g_bucket[b][1][bb][i];
                        bool take = (bb < bin);
                        if (!take) {
                            ull key = ((ull)(r2[n] >> 9) << 17) | n;
                            take = (key <= T);
                        }
                        if (take) {
                            lab[n] = 1;
                            atomicSub(&h3[r3[n] >> 20], 1);
                        }
                    }
                }
            } else {
                for (int n = t * 4; n < N_CNT; n += 4096) {
                    int4 l4 = *(const int4*)&lab[n];
                    const int* lq = (const int*)&l4;
                    bool any0 = (lq[0] == 0) | (lq[1] == 0) | (lq[2] == 0) | (lq[3] == 0);
                    if (!any0) continue;
                    uint4 r4 = *(const uint4*)&r2[n];
                    const unsigned* rq = (const unsigned*)&r4;
#pragma unroll
                    for (int q = 0; q < 4; ++q)
                        if (lq[q] == 0) {
                            ull key = ((ull)(rq[q] >> 9) << 17) | (unsigned)(n + q);
                            if (key <= T) {
                                lab[n + q] = 1;
                                atomicSub(&h3[r3[n + q] >> 20], 1);
                            }
                        }
                }
            }
            __syncthreads();
        }
    }
    // mode 1 demotion and mode 3 promotion are deferred to the scatter kernel.

    int neg2 = (mode == 2) ? neg - K : (mode == 3 ? 0 : neg);
    int sel3 = (neg2 > K_POS);
    if (t == 0) g_sel3[b] = sel3;
    if (sel3) {
        int bin, rank;
        crossing1024(h3, K_POS, bin, rank, warpsum, &s_bin, &s_rank);
        if (t == 0) s_cnt = 0;
        __syncthreads();
        int c3build = ((const int*)g_hist[b][2])[bin];  // build-time count bounds bucket validity
        int c;
        if (c3build <= CAPB) {
            if (t < c3build) {
                unsigned n = g_bucket[b][2][bin][t];
                if (lab[n] == 0) {   // exclude negs promoted in mode 2
                    int idx = atomicAdd(&s_cnt, 1);
                    unsigned rb = r3[n];
                    buf[idx] = (((rb >> 9) & 0x7FFu) << 17) | n;
                }
            }
            __syncthreads();
            c = s_cnt;
        } else {
            for (int n = t * 4; n < N_CNT; n += 4096) {
                int4 l4 = *(const int4*)&lab[n];
                uint4 r4 = *(const uint4*)&r3[n];
                const int* lq = (const int*)&l4;
                const unsigned* rq = (const unsigned*)&r4;
#pragma unroll
                for (int q = 0; q < 4; ++q)
                    if (lq[q] == 0 && (int)(rq[q] >> 20) == bin) {
                        int idx = atomicAdd(&s_cnt, 1);
                        if (idx < CAP)
                            buf[idx] = (((rq[q] >> 9) & 0x7FFu) << 17) | (unsigned)(n + q);
                    }
            }
            __syncthreads();
            c = min(s_cnt, CAP);
        }
        resolve1024(buf, c, rank, bin, &s_thr);
        if (t == 0) g_thr3[b] = s_thr;
    }
}

// ---- final scatter: apply deferred mode-1/3 + stage-3, write labels --------
__global__ __launch_bounds__(256) void scatter_kernel(const int* __restrict__ iidx,
                                                      float* __restrict__ out) {
    int b = blockIdx.y;
    int n0 = blockIdx.x * 1024 + threadIdx.x * 4;
    if (n0 >= N_CNT) return;
    int base = b * N_CNT + n0;
    int4 lab4 = *(const int4*)&g_label[base];
    int labs[4] = {lab4.x, lab4.y, lab4.z, lab4.w};
    int4 idx4 = *(const int4*)&iidx[n0];
    int idxs[4] = {idx4.x, idx4.y, idx4.z, idx4.w};
    int mode = g_mode[b];
    if (mode == 1) {
        bool any1 = (labs[0] == 1) | (labs[1] == 1) | (labs[2] == 1) | (labs[3] == 1);
        if (any1) {
            uint4 rb1 = *(const uint4*)&g_rbits[base];
            const unsigned* r1v = (const unsigned*)&rb1;
            ull T = g_thr12[b];
#pragma unroll
            for (int q = 0; q < 4; ++q)
                if (labs[q] == 1) {
                    ull key = ((ull)(r1v[q] >> 9) << 17) | (unsigned)(n0 + q);
                    if (key > T) labs[q] = -1;
                }
        }
    } else if (mode == 3) {
#pragma unroll
        for (int q = 0; q < 4; ++q)
            if (labs[q] == 0) labs[q] = 1;
    }
    if (g_sel3[b]) {
        bool any0 = (labs[0] == 0) | (labs[1] == 0) | (labs[2] == 0) | (labs[3] == 0);
        if (any0) {
            uint4 rb3 = *(const uint4*)&g_rbits[2 * BN + base];
            const unsigned* r3v = (const unsigned*)&rb3;
            ull T = g_thr3[b];
#pragma unroll
            for (int q = 0; q < 4; ++q)
                if (labs[q] == 0) {
                    ull key = ((ull)(r3v[q] >> 9) << 17) | (unsigned)(n0 + q);
                    if (key > T) labs[q] = -1;
                }
        }
    }
    float* ob = out + (long)b * A_CNT;
#pragma unroll
    for (int q = 0; q < 4; ++q) ob[idxs[q]] = (float)labs[q];
}

// ------------------------------ launch --------------------------------------
extern "C" void kernel_launch(void* const* d_in, const int* in_sizes, int n_in,
                              void* d_out, int out_size) {
    const float* anch = nullptr;   // anchor_boxes        (200000,4) -> 800000
    const float* ianch = nullptr;  // inside_anchor_boxes (100000,4) -> 400000
    const float* gtb = nullptr;    // gt_boxes            (8,64,4)   -> 2048
    const int*   iidx = nullptr;   // inside_index        (100000)
    for (int i = 0; i < n_in; ++i) {
        switch (in_sizes[i]) {
            case 800000: anch  = (const float*)d_in[i]; break;
            case 400000: ianch = (const float*)d_in[i]; break;
            case 2048:   gtb   = (const float*)d_in[i]; break;
            case 100000: iidx  = (const int*)d_in[i];   break;
            default: break;
        }
    }
    float* out = (float*)d_out;
    const long LBL = (long)B_CNT * A_CNT;

    init_rng_kernel<<<(3 * BN + 255) / 256, 256>>>((float4*)out);

    dim3 gF(FBLK, B_CNT);
    fused_kernel<<<gF, 256>>>((const float4*)ianch, (const float4*)gtb,
                              (const float4*)anch, iidx,
                              (float4*)(out + LBL));
    dim3 gR(RBLK, B_CNT);
    repair_hist_kernel<<<gR, 256>>>((const float4*)ianch, (const float4*)gtb);
    sample_kernel<<<B_CNT, 1024>>>();
    dim3 gS(SBLK, B_CNT);
    scatter_kernel<<<gS, 256>>>(iidx, out);
}